// round 7
// baseline (speedup 1.0000x reference)
#include <cuda_runtime.h>
#include <cuda_fp16.h>
#include <cstdint>
#include <math.h>

#define NB 16
#define SEQ 2048
#define DM 768

// ---------------- scratch (device globals) ----------------------------------
__device__ __half g_xt[(long long)NB * SEQ * DM];
__device__ __half g_xf[(long long)NB * SEQ * DM];
__device__ __half g_WqT[DM * DM];
__device__ __half g_WkT[DM * DM];
__device__ __half g_WvT[DM * DM];
__device__ __half g_Q[(long long)NB * SEQ * DM];    // pre-scaled by 1/sqrt(H)
__device__ __half g_K[(long long)NB * SEQ * DM];
__device__ __half g_VT[(long long)NB * SEQ * DM];   // [b][768][2048]
__device__ __half g_E[(long long)NB * SEQ * SEQ];   // exp(scores), fp16
__device__ float  g_inv[(long long)NB * SEQ];       // 1 / rowsum(E)

// ---------------- PTX helpers ------------------------------------------------
__device__ __forceinline__ uint32_t smem_u32(const void* p) {
    return (uint32_t)__cvta_generic_to_shared(p);
}
__device__ __forceinline__ void cp_async16(uint32_t dst, const void* src) {
    asm volatile("cp.async.cg.shared.global [%0], [%1], 16;" :: "r"(dst), "l"(src));
}
__device__ __forceinline__ void cp_commit() {
    asm volatile("cp.async.commit_group;" ::: "memory");
}
__device__ __forceinline__ void ldm_x4(uint32_t* d, uint32_t a) {
    asm volatile("ldmatrix.sync.aligned.m8n8.x4.shared.b16 {%0,%1,%2,%3}, [%4];"
                 : "=r"(d[0]), "=r"(d[1]), "=r"(d[2]), "=r"(d[3]) : "r"(a));
}
__device__ __forceinline__ void mma16816(float* c, const uint32_t* a, const uint32_t* b) {
    asm volatile("mma.sync.aligned.m16n8k16.row.col.f32.f16.f16.f32 "
                 "{%0,%1,%2,%3}, {%4,%5,%6,%7}, {%8,%9}, {%0,%1,%2,%3};"
                 : "+f"(c[0]), "+f"(c[1]), "+f"(c[2]), "+f"(c[3])
                 : "r"(a[0]), "r"(a[1]), "r"(a[2]), "r"(a[3]),
                   "r"(b[0]), "r"(b[1]));
}

// ============================================================================
// GEMM: C[M,N] = A[M,K] * B[N,K]^T, fp16 in, fp32 accum (mma.sync).
// BM=128, BN=256, BK=64, 4 stages SW128, 512 threads, PF=2, one sync/tile.
// MODE: 0 *scale   1 +bias[n],*scale   2 +bias[m]
//       3 exp(acc) -> half              4 acc * rowscale[m]
// (Exact round-5 codegen shape — do not grow this template: it sits at the
//  128-reg __launch_bounds__ ceiling and added state regressed 1.9x.)
// ============================================================================
template <int MODE, bool OUT_HALF>
__global__ void __launch_bounds__(512, 1)
gemm_any(const __half* __restrict__ Ag, const __half* __restrict__ Bg,
         const float* __restrict__ bias, void* __restrict__ Cg,
         int Kd, int lda, int ldb, int ldc, float scale,
         long long strA, long long strB, long long strC, long long strBias)
{
    constexpr int BM = 128, BN = 256, BK = 64, ST = 4, PF = 2;
    constexpr int ABYTES = BM * 128;            // 16 KB
    constexpr int BBYTES = BN * 128;            // 32 KB
    constexpr int STAGE  = ABYTES + BBYTES;     // 48 KB

    extern __shared__ char dsm[];
    const uint32_t smem0 = (smem_u32(dsm) + 1023u) & ~1023u;

    const int tid  = threadIdx.x;
    const int warp = tid >> 5;
    const int lane = tid & 31;
    const int z    = blockIdx.z;
    const int row0 = blockIdx.y * BM;
    const int col0 = blockIdx.x * BN;

    const __half* Az = Ag + (size_t)z * strA;
    const __half* Bz = Bg + (size_t)z * strB;
    const float* bz = bias ? (bias + (size_t)z * strBias) : bias;
    const int T = Kd / BK;

    auto load = [&](int s, int t) {
        const int kt = t * BK;
        const uint32_t abase = smem0 + s * STAGE;
        const uint32_t bbase = abase + ABYTES;
#pragma unroll
        for (int it = 0; it < 2; ++it) {            // A: 1024 x 16B
            int id = tid + it * 512;
            int r = id >> 3, cb = (id & 7) << 4;
            uint32_t off = (uint32_t)(r * 128 + cb);
            cp_async16(abase + (off ^ ((off >> 3) & 0x70)),
                       Az + (size_t)(row0 + r) * lda + kt + (cb >> 1));
        }
#pragma unroll
        for (int it = 0; it < 4; ++it) {            // B: 2048 x 16B
            int id = tid + it * 512;
            int r = id >> 3, cb = (id & 7) << 4;
            uint32_t off = (uint32_t)(r * 128 + cb);
            cp_async16(bbase + (off ^ ((off >> 3) & 0x70)),
                       Bz + (size_t)(col0 + r) * ldb + kt + (cb >> 1));
        }
    };

    const int wr = warp >> 2;       // 0..3 : 32-row slab
    const int wc = warp & 3;        // 0..3 : 64-col slab
    float acc[2][8][4];
#pragma unroll
    for (int i = 0; i < 2; ++i)
#pragma unroll
        for (int j = 0; j < 8; ++j)
#pragma unroll
            for (int r = 0; r < 4; ++r) acc[i][j][r] = 0.f;

    load(0, 0); cp_commit();
    load(1, 1); cp_commit();

    for (int i = 0; i < T; ++i) {
        const int j = i + PF;
        if (j < T) load(j % ST, j);
        cp_commit();
        asm volatile("cp.async.wait_group 2;" ::: "memory");
        __syncthreads();

        const uint32_t ab = smem0 + (i % ST) * STAGE;
        const uint32_t bb = ab + ABYTES;
#pragma unroll
        for (int ks = 0; ks < 4; ++ks) {
            const int kb = ks * 32;
            const int rl = lane & 15;
            const int ch = kb + ((lane >> 4) << 4);
            uint32_t a[2][4], bq[4][4];
#pragma unroll
            for (int ii = 0; ii < 2; ++ii) {
                int row = wr * 32 + ii * 16 + rl;
                ldm_x4(a[ii], ab + row * 128 + (ch ^ ((row & 7) << 4)));
            }
#pragma unroll
            for (int jj = 0; jj < 4; ++jj) {
                int row = wc * 64 + jj * 16 + rl;
                ldm_x4(bq[jj], bb + row * 128 + (ch ^ ((row & 7) << 4)));
            }
#pragma unroll
            for (int ii = 0; ii < 2; ++ii)
#pragma unroll
                for (int jj = 0; jj < 4; ++jj) {
                    uint32_t b0[2] = { bq[jj][0], bq[jj][2] };
                    uint32_t b1[2] = { bq[jj][1], bq[jj][3] };
                    mma16816(acc[ii][2 * jj],     a[ii], b0);
                    mma16816(acc[ii][2 * jj + 1], a[ii], b1);
                }
        }
        // no trailing sync: stage i%4 next written at iter i+2, after sync(i+1)
    }

    // ---- epilogue ----
    const int r0 = row0 + wr * 32 + (lane >> 2);
    const int c0 = col0 + wc * 64 + ((lane & 3) << 1);
#pragma unroll
    for (int ii = 0; ii < 2; ++ii) {
        const int r = r0 + ii * 16;
        float rf0 = 0.f, rf8 = 0.f;
        if (MODE == 2 || MODE == 4) { rf0 = bz[r]; rf8 = bz[r + 8]; }
#pragma unroll
        for (int jj = 0; jj < 8; ++jj) {
            const int c = c0 + jj * 8;
            float v0 = acc[ii][jj][0], v1 = acc[ii][jj][1];
            float v2 = acc[ii][jj][2], v3 = acc[ii][jj][3];
            if (MODE == 1) {
                float b0 = bz[c], b1 = bz[c + 1];
                v0 = (v0 + b0) * scale; v1 = (v1 + b1) * scale;
                v2 = (v2 + b0) * scale; v3 = (v3 + b1) * scale;
            } else if (MODE == 2) {
                v0 += rf0; v1 += rf0; v2 += rf8; v3 += rf8;
            } else if (MODE == 3) {
                v0 = __expf(v0); v1 = __expf(v1);
                v2 = __expf(v2); v3 = __expf(v3);
            } else if (MODE == 4) {
                v0 *= rf0; v1 *= rf0; v2 *= rf8; v3 *= rf8;
            } else {
                v0 *= scale; v1 *= scale; v2 *= scale; v3 *= scale;
            }
            if constexpr (OUT_HALF) {
                __half* C = (__half*)Cg + (size_t)z * strC;
                *(__half2*)(C + (size_t)r * ldc + c)       = __floats2half2_rn(v0, v1);
                *(__half2*)(C + (size_t)(r + 8) * ldc + c) = __floats2half2_rn(v2, v3);
            } else {
                float* C = (float*)Cg + (size_t)z * strC;
                *(float2*)(C + (size_t)r * ldc + c)       = make_float2(v0, v1);
                *(float2*)(C + (size_t)(r + 8) * ldc + c) = make_float2(v2, v3);
            }
        }
    }
}

// ---------------- fp32 -> fp16 convert, both inputs in one launch ------------
__global__ void __launch_bounds__(256)
cvt2_k(const float4* __restrict__ in0, __half2* __restrict__ out0,
       const float4* __restrict__ in1, __half2* __restrict__ out1, int n4)
{
    int i = blockIdx.x * 256 + threadIdx.x;
    const float4* in = (i < n4) ? in0 : in1;
    __half2* out = (i < n4) ? out0 : out1;
    int k = (i < n4) ? i : (i - n4);
    float4 v = in[k];
    out[2 * k]     = __floats2half2_rn(v.x, v.y);
    out[2 * k + 1] = __floats2half2_rn(v.z, v.w);
}

// ---------------- fp32 [768,768] -> fp16 transposed --------------------------
__global__ void __launch_bounds__(256)
cvtT_k(const float* __restrict__ in, __half* __restrict__ out)
{
    __shared__ float t[32][33];
    const int bx = blockIdx.x * 32;
    const int by = blockIdx.y * 32;
    const int tx = threadIdx.x, ty = threadIdx.y;
#pragma unroll
    for (int yy = ty; yy < 32; yy += 8)
        t[yy][tx] = in[(size_t)(by + yy) * DM + bx + tx];
    __syncthreads();
#pragma unroll
    for (int yy = ty; yy < 32; yy += 8)
        out[(size_t)(bx + yy) * DM + by + tx] = __float2half(t[tx][yy]);
}

// ---------------- rowsum: inv[row] = 1 / sum(E[row, 0:2048]) -----------------
__global__ void __launch_bounds__(256)
rowsum_k(const __half* __restrict__ E, float* __restrict__ inv)
{
    const size_t row = blockIdx.x;
    const __half* e = E + row * (size_t)SEQ;
    const int t = threadIdx.x;

    uint4 raw = *(const uint4*)(e + 8 * t);
    __half2 h[4] = {*(__half2*)&raw.x, *(__half2*)&raw.y,
                    *(__half2*)&raw.z, *(__half2*)&raw.w};
    float sum = 0.f;
#pragma unroll
    for (int i = 0; i < 4; ++i) {
        float2 f = __half22float2(h[i]);
        sum += f.x + f.y;
    }
    __shared__ float ssum[8];
#pragma unroll
    for (int o = 16; o; o >>= 1) sum += __shfl_xor_sync(0xffffffffu, sum, o);
    if ((t & 31) == 0) ssum[t >> 5] = sum;
    __syncthreads();
    if (t == 0) {
        float s = ssum[0];
#pragma unroll
        for (int i = 1; i < 8; ++i) s += ssum[i];
        inv[row] = 1.0f / s;
    }
}

// ---------------- launch ------------------------------------------------------
extern "C" void kernel_launch(void* const* d_in, const int* in_sizes, int n_in,
                              void* d_out, int out_size)
{
    const float* x_to   = (const float*)d_in[0];
    const float* x_from = (const float*)d_in[1];
    const float* Wq = (const float*)d_in[2];
    const float* bq = (const float*)d_in[3];
    const float* Wk = (const float*)d_in[4];
    const float* bk = (const float*)d_in[5];
    const float* Wv = (const float*)d_in[6];
    const float* bv = (const float*)d_in[7];
    float* out = (float*)d_out;

    void *pxt, *pxf, *pWqT, *pWkT, *pWvT, *pQ, *pK, *pVT, *pE, *pInv;
    cudaGetSymbolAddress(&pxt, g_xt);
    cudaGetSymbolAddress(&pxf, g_xf);
    cudaGetSymbolAddress(&pWqT, g_WqT);
    cudaGetSymbolAddress(&pWkT, g_WkT);
    cudaGetSymbolAddress(&pWvT, g_WvT);
    cudaGetSymbolAddress(&pQ, g_Q);
    cudaGetSymbolAddress(&pK, g_K);
    cudaGetSymbolAddress(&pVT, g_VT);
    cudaGetSymbolAddress(&pE, g_E);
    cudaGetSymbolAddress(&pInv, g_inv);

    constexpr int SMEM = 4 * 49152 + 1024;   // 197,632 B
    cudaFuncSetAttribute((const void*)gemm_any<1, true>,
                         cudaFuncAttributeMaxDynamicSharedMemorySize, SMEM);
    cudaFuncSetAttribute((const void*)gemm_any<2, true>,
                         cudaFuncAttributeMaxDynamicSharedMemorySize, SMEM);
    cudaFuncSetAttribute((const void*)gemm_any<3, true>,
                         cudaFuncAttributeMaxDynamicSharedMemorySize, SMEM);
    cudaFuncSetAttribute((const void*)gemm_any<4, false>,
                         cudaFuncAttributeMaxDynamicSharedMemorySize, SMEM);

    // converts (both x arrays in one launch; boundary is block-aligned)
    const int nx4 = (NB * SEQ * DM) / 4;     // 6,291,456 = 24576 * 256
    cvt2_k<<<(2 * nx4) / 256, 256>>>((const float4*)x_to, (__half2*)pxt,
                                     (const float4*)x_from, (__half2*)pxf, nx4);
    dim3 tb(32, 8), tg(DM / 32, DM / 32);
    cvtT_k<<<tg, tb>>>(Wq, (__half*)pWqT);
    cvtT_k<<<tg, tb>>>(Wk, (__half*)pWkT);
    cvtT_k<<<tg, tb>>>(Wv, (__half*)pWvT);

    const float qscale = 1.0f / sqrtf((float)DM);

    // Q = xt * WqT^T (+bq)*qscale ; K = xf * WkT^T (+bk)
    dim3 gq(DM / 256, (NB * SEQ) / 128, 1);
    gemm_any<1, true><<<gq, 512, SMEM>>>(
        (const __half*)pxt, (const __half*)pWqT, bq, pQ,
        DM, DM, DM, DM, qscale, 0, 0, 0, 0);
    gemm_any<1, true><<<gq, 512, SMEM>>>(
        (const __half*)pxf, (const __half*)pWkT, bk, pK,
        DM, DM, DM, DM, 1.0f, 0, 0, 0, 0);

    // V^T = WvT * xf^T (+bv per row), batched
    dim3 gvt(SEQ / 256, DM / 128, NB);
    gemm_any<2, true><<<gvt, 512, SMEM>>>(
        (const __half*)pWvT, (const __half*)pxf, bv, pVT,
        DM, DM, DM, SEQ, 1.0f, 0, (long long)SEQ * DM, (long long)DM * SEQ, 0);

    // E = exp(Q * K^T), batched, fp16 out
    dim3 gs(SEQ / 256, SEQ / 128, NB);
    gemm_any<3, true><<<gs, 512, SMEM>>>(
        (const __half*)pQ, (const __half*)pK, nullptr, pE,
        DM, DM, DM, SEQ, 1.0f,
        (long long)SEQ * DM, (long long)SEQ * DM, (long long)SEQ * SEQ, 0);

    // inv[row] = 1 / rowsum(E)
    rowsum_k<<<NB * SEQ, 256>>>((const __half*)pE, (float*)pInv);

    // out = (E * V) * inv[row], batched, fp32 out
    dim3 go(DM / 256, SEQ / 128, NB);
    gemm_any<4, false><<<go, 512, SMEM>>>(
        (const __half*)pE, (const __half*)pVT, (const float*)pInv, out,
        SEQ, SEQ, SEQ, DM, 1.0f,
        (long long)SEQ * SEQ, (long long)DM * SEQ, (long long)SEQ * DM, SEQ);
}

// round 8
// speedup vs baseline: 1.9098x; 1.9098x over previous
#include <cuda_runtime.h>
#include <cuda_fp16.h>
#include <cstdint>
#include <math.h>

#define NB 16
#define SEQ 2048
#define DM 768

#if defined(__CUDA_ARCH_FEAT_SM103_ALL) || defined(__CUDA_ARCH_FEAT_SM100_ALL)
#define TC_PATH 1
#else
#define TC_PATH 0
#endif

// ---------------- scratch (device globals) ----------------------------------
__device__ __half g_xt[(long long)NB * SEQ * DM];
__device__ __half g_xf[(long long)NB * SEQ * DM];
__device__ __half g_WqT[DM * DM];
__device__ __half g_WkT[DM * DM];
__device__ __half g_WvT[DM * DM];
__device__ __half g_Q[(long long)NB * SEQ * DM];    // pre-scaled by 1/sqrt(H)
__device__ __half g_K[(long long)NB * SEQ * DM];
__device__ __half g_VT[(long long)NB * SEQ * DM];   // [b][768][2048]
__device__ __half g_E[(long long)NB * SEQ * SEQ];   // exp(scores), fp16
__device__ float  g_inv[(long long)NB * SEQ];       // 1 / rowsum(E)

// ---------------- common PTX helpers -----------------------------------------
__device__ __forceinline__ uint32_t smem_u32(const void* p) {
    return (uint32_t)__cvta_generic_to_shared(p);
}
__device__ __forceinline__ void cp_async16(uint32_t dst, const void* src) {
    asm volatile("cp.async.cg.shared.global [%0], [%1], 16;" :: "r"(dst), "l"(src));
}
__device__ __forceinline__ void cp_commit() {
    asm volatile("cp.async.commit_group;" ::: "memory");
}
__device__ __forceinline__ void ldm_x4(uint32_t* d, uint32_t a) {
    asm volatile("ldmatrix.sync.aligned.m8n8.x4.shared.b16 {%0,%1,%2,%3}, [%4];"
                 : "=r"(d[0]), "=r"(d[1]), "=r"(d[2]), "=r"(d[3]) : "r"(a));
}
__device__ __forceinline__ void mma16816(float* c, const uint32_t* a, const uint32_t* b) {
    asm volatile("mma.sync.aligned.m16n8k16.row.col.f32.f16.f16.f32 "
                 "{%0,%1,%2,%3}, {%4,%5,%6,%7}, {%8,%9}, {%0,%1,%2,%3};"
                 : "+f"(c[0]), "+f"(c[1]), "+f"(c[2]), "+f"(c[3])
                 : "r"(a[0]), "r"(a[1]), "r"(a[2]), "r"(a[3]),
                   "r"(b[0]), "r"(b[1]));
}

// ---------------- tcgen05 helpers (dead code under compute_103) --------------
__device__ __forceinline__ uint32_t elect_one() {
    uint32_t pred;
    asm volatile("{\n .reg .pred p;\n elect.sync _|p, 0xFFFFFFFF;\n"
                 " selp.b32 %0, 1, 0, p;\n}" : "=r"(pred));
    return pred;
}
#define MBAR_INIT(addr, cnt) \
    asm volatile("mbarrier.init.shared.b64 [%0], %1;" :: "r"(addr), "r"(cnt) : "memory")
#define MBAR_WAIT(addr, par) do {                                              \
    uint32_t _m = (addr); uint32_t _p = (par); uint32_t _done;                 \
    asm volatile("{\n .reg .pred p;\n"                                         \
        " mbarrier.try_wait.parity.acquire.cta.shared::cta.b64 p, [%1], %2;\n" \
        " selp.b32 %0, 1, 0, p;\n}"                                            \
        : "=r"(_done) : "r"(_m), "r"(_p) : "memory");                          \
    if (!_done) {                                                              \
        asm volatile("{\n .reg .pred P1;\n"                                    \
            "W_%=:\n"                                                          \
            " mbarrier.try_wait.parity.acquire.cta.shared::cta.b64 P1, [%0], %1, 0x989680;\n" \
            " @P1 bra.uni D_%=;\n bra.uni W_%=;\n"                             \
            "D_%=:\n}" :: "r"(_m), "r"(_p) : "memory");                        \
    }                                                                          \
} while (0)
#if TC_PATH
#define TC_ALLOC(slot, n) \
    asm volatile("tcgen05.alloc.cta_group::1.sync.aligned.shared::cta.b32 [%0], %1;" \
                 :: "r"(slot), "r"(n) : "memory")
#define TC_DEALLOC(t, n) \
    asm volatile("tcgen05.dealloc.cta_group::1.sync.aligned.b32 %0, %1;" :: "r"(t), "r"(n))
#define TC_RELINQ() \
    asm volatile("tcgen05.relinquish_alloc_permit.cta_group::1.sync.aligned;")
#define TC_COMMIT(mbar) \
    asm volatile("tcgen05.commit.cta_group::1.mbarrier::arrive::one.shared::cluster.b64 [%0];" \
                 :: "r"(mbar) : "memory")
#define TC_FENCE_AFTER()  asm volatile("tcgen05.fence::after_thread_sync;" ::: "memory")
#define TC_FENCE_BEFORE() asm volatile("tcgen05.fence::before_thread_sync;" ::: "memory")
#define TC_WAIT_LD()      asm volatile("tcgen05.wait::ld.sync.aligned;" ::: "memory")
#define TC_LD_X32(r, addr) \
    asm volatile("tcgen05.ld.sync.aligned.32x32b.x32.b32 " \
        "{%0,%1,%2,%3,%4,%5,%6,%7,%8,%9,%10,%11,%12,%13,%14,%15," \
        "%16,%17,%18,%19,%20,%21,%22,%23,%24,%25,%26,%27,%28,%29,%30,%31}, [%32];" \
        : "=r"((r)[0]),"=r"((r)[1]),"=r"((r)[2]),"=r"((r)[3]),                  \
          "=r"((r)[4]),"=r"((r)[5]),"=r"((r)[6]),"=r"((r)[7]),                  \
          "=r"((r)[8]),"=r"((r)[9]),"=r"((r)[10]),"=r"((r)[11]),                \
          "=r"((r)[12]),"=r"((r)[13]),"=r"((r)[14]),"=r"((r)[15]),              \
          "=r"((r)[16]),"=r"((r)[17]),"=r"((r)[18]),"=r"((r)[19]),              \
          "=r"((r)[20]),"=r"((r)[21]),"=r"((r)[22]),"=r"((r)[23]),              \
          "=r"((r)[24]),"=r"((r)[25]),"=r"((r)[26]),"=r"((r)[27]),              \
          "=r"((r)[28]),"=r"((r)[29]),"=r"((r)[30]),"=r"((r)[31])               \
        : "r"(addr))

static constexpr uint64_t DESC_BASE_SW128 =
    (uint64_t(2) << 61) | (uint64_t(1) << 46) | (uint64_t(64) << 32) | (uint64_t(1) << 16);
__device__ __forceinline__ uint64_t make_desc(uint32_t addr) {
    return DESC_BASE_SW128 | ((uint64_t)(addr >> 4) & 0x3FFF);
}
__device__ __forceinline__ void mma_f16_ss(uint32_t d, uint64_t ad, uint64_t bd,
                                           uint32_t idesc, uint32_t acc) {
    asm volatile("{\n .reg .pred p;\n setp.ne.u32 p, %5, 0;\n"
        " tcgen05.mma.cta_group::1.kind::f16 [%0], %1, %2, %3, {%4,%4,%4,%4}, p;\n}"
        :: "r"(d), "l"(ad), "l"(bd), "r"(idesc), "r"(0u), "r"(acc) : "memory");
}
#endif

// ============================================================================
// Unified GEMM: C[M,N] = A[M,K] * B[N,K]^T, fp16 in, fp32 accum.
// BM=128, BN=256, BK=64, 4 stages SW128, 512 threads, PF=2, ONE sync/tile.
// MODE: 0 plain(*scale)  1 +bias[n], *scale  2 +bias[m]
//       3 exp(acc) (OUT_HALF)                4 acc * rowscale[m] (array)
// ============================================================================
template <int MODE, bool OUT_HALF>
__global__ void __launch_bounds__(512, 1)
gemm_any(const __half* __restrict__ Ag, const __half* __restrict__ Bg,
         const float* __restrict__ bias, void* __restrict__ Cg,
         int Kd, int lda, int ldb, int ldc, float scale,
         long long strA, long long strB, long long strC, long long strBias)
{
    constexpr int BM = 128, BN = 256, BK = 64, ST = 4, PF = 2;
    constexpr int ABYTES = BM * 128;            // 16 KB
    constexpr int BBYTES = BN * 128;            // 32 KB
    constexpr int STAGE  = ABYTES + BBYTES;     // 48 KB

    extern __shared__ char dsm[];
    const uint32_t smem0 = (smem_u32(dsm) + 1023u) & ~1023u;

    const int tid  = threadIdx.x;
    const int warp = tid >> 5;
    const int lane = tid & 31;
    const int z    = blockIdx.z;
    const int row0 = blockIdx.y * BM;
    const int col0 = blockIdx.x * BN;

    const __half* Az = Ag + (size_t)z * strA;
    const __half* Bz = Bg + (size_t)z * strB;
    const float* bz = bias ? (bias + (size_t)z * strBias) : bias;
    const int T = Kd / BK;

    auto load = [&](int s, int t) {
        const int kt = t * BK;
        const uint32_t abase = smem0 + s * STAGE;
        const uint32_t bbase = abase + ABYTES;
#pragma unroll
        for (int it = 0; it < 2; ++it) {            // A: 1024 x 16B
            int id = tid + it * 512;
            int r = id >> 3, cb = (id & 7) << 4;
            uint32_t off = (uint32_t)(r * 128 + cb);
            cp_async16(abase + (off ^ ((off >> 3) & 0x70)),
                       Az + (size_t)(row0 + r) * lda + kt + (cb >> 1));
        }
#pragma unroll
        for (int it = 0; it < 4; ++it) {            // B: 2048 x 16B
            int id = tid + it * 512;
            int r = id >> 3, cb = (id & 7) << 4;
            uint32_t off = (uint32_t)(r * 128 + cb);
            cp_async16(bbase + (off ^ ((off >> 3) & 0x70)),
                       Bz + (size_t)(col0 + r) * ldb + kt + (cb >> 1));
        }
    };

#if TC_PATH
    __shared__ __align__(8) uint64_t mbar[ST];
    __shared__ uint32_t tmem_slot;
    if (warp == 0) TC_ALLOC(smem_u32(&tmem_slot), 256);
    if (tid == 0) {
#pragma unroll
        for (int s = 0; s < ST; ++s) MBAR_INIT(smem_u32(&mbar[s]), 1);
    }
    __syncthreads();
    uint32_t tmem;
    asm volatile("ld.shared.b32 %0, [%1];" : "=r"(tmem) : "r"(smem_u32(&tmem_slot)));
    constexpr uint32_t IDESC = (1u << 4) | ((BN / 8) << 17) | ((BM / 16) << 24);
#else
    const int wr = warp >> 2;       // 0..3 : 32-row slab
    const int wc = warp & 3;        // 0..3 : 64-col slab
    float acc[2][8][4];
#pragma unroll
    for (int i = 0; i < 2; ++i)
#pragma unroll
        for (int j = 0; j < 8; ++j)
#pragma unroll
            for (int r = 0; r < 4; ++r) acc[i][j][r] = 0.f;
#endif

    // prologue: 2 tiles in flight
    load(0, 0); cp_commit();
    load(1, 1); cp_commit();

    for (int i = 0; i < T; ++i) {
        const int j = i + PF;
        if (j < T) {
#if TC_PATH
            if (j >= ST) MBAR_WAIT(smem_u32(&mbar[j % ST]), ((j / ST) - 1) & 1);
#endif
            load(j % ST, j);
        }
        cp_commit();
        asm volatile("cp.async.wait_group 2;" ::: "memory");
#if TC_PATH
        asm volatile("fence.proxy.async.shared::cta;" ::: "memory");
#endif
        __syncthreads();

#if TC_PATH
        if (warp == 0 && elect_one()) {
            const int s = i % ST;
            const uint64_t ad = make_desc(smem0 + s * STAGE);
            const uint64_t bd = make_desc(smem0 + s * STAGE + ABYTES);
#pragma unroll
            for (int k = 0; k < 4; ++k)
                mma_f16_ss(tmem, ad + k * 2, bd + k * 2, IDESC,
                           (i > 0 || k > 0) ? 1u : 0u);
            TC_COMMIT(smem_u32(&mbar[i % ST]));
        }
        __syncthreads();   // TC path keeps trailing sync (mbar pacing differs)
#else
        const uint32_t ab = smem0 + (i % ST) * STAGE;
        const uint32_t bb = ab + ABYTES;
#pragma unroll
        for (int ks = 0; ks < 4; ++ks) {
            const int kb = ks * 32;
            const int rl = lane & 15;
            const int ch = kb + ((lane >> 4) << 4);
            uint32_t a[2][4], bq[4][4];
#pragma unroll
            for (int ii = 0; ii < 2; ++ii) {
                int row = wr * 32 + ii * 16 + rl;
                ldm_x4(a[ii], ab + row * 128 + (ch ^ ((row & 7) << 4)));
            }
#pragma unroll
            for (int jj = 0; jj < 4; ++jj) {
                int row = wc * 64 + jj * 16 + rl;
                ldm_x4(bq[jj], bb + row * 128 + (ch ^ ((row & 7) << 4)));
            }
#pragma unroll
            for (int ii = 0; ii < 2; ++ii)
#pragma unroll
                for (int jj = 0; jj < 4; ++jj) {
                    uint32_t b0[2] = { bq[jj][0], bq[jj][2] };
                    uint32_t b1[2] = { bq[jj][1], bq[jj][3] };
                    mma16816(acc[ii][2 * jj],     a[ii], b0);
                    mma16816(acc[ii][2 * jj + 1], a[ii], b1);
                }
        }
        // no trailing sync: stage i%4 is next written at iter i+2, after sync(i+1)
#endif
    }

#if TC_PATH
    MBAR_WAIT(smem_u32(&mbar[(T - 1) % ST]), ((T - 1) / ST) & 1);
    TC_FENCE_AFTER();
    const int sub = warp & 3;
    const int cg  = warp >> 2;
    const int r   = row0 + sub * 32 + lane;
    const uint32_t taddr = tmem + cg * 64;
    float rowf = 0.f;
    if (MODE == 2) rowf = bz[r];
    if (MODE == 4) rowf = bz[r];
    uint32_t d[32];
#pragma unroll
    for (int h = 0; h < 2; ++h) {
        TC_LD_X32(d, taddr + h * 32);
        TC_WAIT_LD();
        const int cbase = col0 + cg * 64 + h * 32;
        float v[32];
#pragma unroll
        for (int jj = 0; jj < 32; ++jj) {
            float x = __uint_as_float(d[jj]);
            if (MODE == 1)      v[jj] = (x + bz[cbase + jj]) * scale;
            else if (MODE == 2) v[jj] = x + rowf;
            else if (MODE == 3) v[jj] = __expf(x);
            else if (MODE == 4) v[jj] = x * rowf;
            else                v[jj] = x * scale;
        }
        if constexpr (OUT_HALF) {
            __half2 hb[16];
#pragma unroll
            for (int jj = 0; jj < 16; ++jj)
                hb[jj] = __floats2half2_rn(v[2 * jj], v[2 * jj + 1]);
            uint4* dst = (uint4*)((__half*)Cg + (size_t)z * strC + (size_t)r * ldc + cbase);
#pragma unroll
            for (int q = 0; q < 4; ++q) dst[q] = ((uint4*)hb)[q];
        } else {
            float4* dst = (float4*)((float*)Cg + (size_t)z * strC + (size_t)r * ldc + cbase);
#pragma unroll
            for (int q = 0; q < 8; ++q) dst[q] = ((float4*)v)[q];
        }
    }
    TC_FENCE_BEFORE();
    __syncthreads();
    if (warp == 0) { TC_RELINQ(); TC_DEALLOC(tmem, 256); }
#else
    const int r0 = row0 + wr * 32 + (lane >> 2);
    const int c0 = col0 + wc * 64 + ((lane & 3) << 1);
#pragma unroll
    for (int ii = 0; ii < 2; ++ii) {
        const int r = r0 + ii * 16;
        float rf0 = 0.f, rf8 = 0.f;
        if (MODE == 2 || MODE == 4) { rf0 = bz[r]; rf8 = bz[r + 8]; }
#pragma unroll
        for (int jj = 0; jj < 8; ++jj) {
            const int c = c0 + jj * 8;
            float v0 = acc[ii][jj][0], v1 = acc[ii][jj][1];
            float v2 = acc[ii][jj][2], v3 = acc[ii][jj][3];
            if (MODE == 1) {
                float b0 = bz[c], b1 = bz[c + 1];
                v0 = (v0 + b0) * scale; v1 = (v1 + b1) * scale;
                v2 = (v2 + b0) * scale; v3 = (v3 + b1) * scale;
            } else if (MODE == 2) {
                v0 += rf0; v1 += rf0; v2 += rf8; v3 += rf8;
            } else if (MODE == 3) {
                v0 = __expf(v0); v1 = __expf(v1);
                v2 = __expf(v2); v3 = __expf(v3);
            } else if (MODE == 4) {
                v0 *= rf0; v1 *= rf0; v2 *= rf8; v3 *= rf8;
            } else {
                v0 *= scale; v1 *= scale; v2 *= scale; v3 *= scale;
            }
            if constexpr (OUT_HALF) {
                __half* C = (__half*)Cg + (size_t)z * strC;
                *(__half2*)(C + (size_t)r * ldc + c)       = __floats2half2_rn(v0, v1);
                *(__half2*)(C + (size_t)(r + 8) * ldc + c) = __floats2half2_rn(v2, v3);
            } else {
                float* C = (float*)Cg + (size_t)z * strC;
                *(float2*)(C + (size_t)r * ldc + c)       = make_float2(v0, v1);
                *(float2*)(C + (size_t)(r + 8) * ldc + c) = make_float2(v2, v3);
            }
        }
    }
#endif
}

// ---------------- fp32 -> fp16 convert ---------------------------------------
__global__ void __launch_bounds__(256)
cvt_k(const float4* __restrict__ in, __half2* __restrict__ out, int n4)
{
    int i = blockIdx.x * 256 + threadIdx.x;
    if (i < n4) {
        float4 v = in[i];
        out[2 * i]     = __floats2half2_rn(v.x, v.y);
        out[2 * i + 1] = __floats2half2_rn(v.z, v.w);
    }
}

// ---------------- fp32 [768,768] -> fp16 transposed --------------------------
__global__ void __launch_bounds__(256)
cvtT_k(const float* __restrict__ in, __half* __restrict__ out)
{
    __shared__ float t[32][33];
    const int bx = blockIdx.x * 32;
    const int by = blockIdx.y * 32;
    const int tx = threadIdx.x, ty = threadIdx.y;
#pragma unroll
    for (int yy = ty; yy < 32; yy += 8)
        t[yy][tx] = in[(size_t)(by + yy) * DM + bx + tx];
    __syncthreads();
#pragma unroll
    for (int yy = ty; yy < 32; yy += 8)
        out[(size_t)(bx + yy) * DM + by + tx] = __float2half(t[tx][yy]);
}

// ---------------- rowsum: inv[row] = 1 / sum(E[row, 0:2048]) -----------------
__global__ void __launch_bounds__(256)
rowsum_k(const __half* __restrict__ E, float* __restrict__ inv)
{
    const size_t row = blockIdx.x;
    const __half* e = E + row * (size_t)SEQ;
    const int t = threadIdx.x;

    uint4 raw = *(const uint4*)(e + 8 * t);
    __half2 h[4] = {*(__half2*)&raw.x, *(__half2*)&raw.y,
                    *(__half2*)&raw.z, *(__half2*)&raw.w};
    float sum = 0.f;
#pragma unroll
    for (int i = 0; i < 4; ++i) {
        float2 f = __half22float2(h[i]);
        sum += f.x + f.y;
    }
    __shared__ float ssum[8];
#pragma unroll
    for (int o = 16; o; o >>= 1) sum += __shfl_xor_sync(0xffffffffu, sum, o);
    if ((t & 31) == 0) ssum[t >> 5] = sum;
    __syncthreads();
    if (t == 0) {
        float s = ssum[0];
#pragma unroll
        for (int i = 1; i < 8; ++i) s += ssum[i];
        inv[row] = 1.0f / s;
    }
}

// ---------------- launch ------------------------------------------------------
extern "C" void kernel_launch(void* const* d_in, const int* in_sizes, int n_in,
                              void* d_out, int out_size)
{
    const float* x_to   = (const float*)d_in[0];
    const float* x_from = (const float*)d_in[1];
    const float* Wq = (const float*)d_in[2];
    const float* bq = (const float*)d_in[3];
    const float* Wk = (const float*)d_in[4];
    const float* bk = (const float*)d_in[5];
    const float* Wv = (const float*)d_in[6];
    const float* bv = (const float*)d_in[7];
    float* out = (float*)d_out;

    void *pxt, *pxf, *pWqT, *pWkT, *pWvT, *pQ, *pK, *pVT, *pE, *pInv;
    cudaGetSymbolAddress(&pxt, g_xt);
    cudaGetSymbolAddress(&pxf, g_xf);
    cudaGetSymbolAddress(&pWqT, g_WqT);
    cudaGetSymbolAddress(&pWkT, g_WkT);
    cudaGetSymbolAddress(&pWvT, g_WvT);
    cudaGetSymbolAddress(&pQ, g_Q);
    cudaGetSymbolAddress(&pK, g_K);
    cudaGetSymbolAddress(&pVT, g_VT);
    cudaGetSymbolAddress(&pE, g_E);
    cudaGetSymbolAddress(&pInv, g_inv);

    constexpr int SMEM = 4 * 49152 + 1024;   // 197,632 B
    cudaFuncSetAttribute((const void*)gemm_any<1, true>,
                         cudaFuncAttributeMaxDynamicSharedMemorySize, SMEM);
    cudaFuncSetAttribute((const void*)gemm_any<2, true>,
                         cudaFuncAttributeMaxDynamicSharedMemorySize, SMEM);
    cudaFuncSetAttribute((const void*)gemm_any<3, true>,
                         cudaFuncAttributeMaxDynamicSharedMemorySize, SMEM);
    cudaFuncSetAttribute((const void*)gemm_any<4, false>,
                         cudaFuncAttributeMaxDynamicSharedMemorySize, SMEM);

    // converts
    const int nx4 = (NB * SEQ * DM) / 4;
    cvt_k<<<(nx4 + 255) / 256, 256>>>((const float4*)x_to,   (__half2*)pxt, nx4);
    cvt_k<<<(nx4 + 255) / 256, 256>>>((const float4*)x_from, (__half2*)pxf, nx4);
    dim3 tb(32, 8), tg(DM / 32, DM / 32);
    cvtT_k<<<tg, tb>>>(Wq, (__half*)pWqT);
    cvtT_k<<<tg, tb>>>(Wk, (__half*)pWkT);
    cvtT_k<<<tg, tb>>>(Wv, (__half*)pWvT);

    const float qscale = 1.0f / sqrtf((float)DM);

    // Q = xt * WqT^T (+bq)*qscale ; K = xf * WkT^T (+bk)
    dim3 gq(DM / 256, (NB * SEQ) / 128, 1);
    gemm_any<1, true><<<gq, 512, SMEM>>>(
        (const __half*)pxt, (const __half*)pWqT, bq, pQ,
        DM, DM, DM, DM, qscale, 0, 0, 0, 0);
    gemm_any<1, true><<<gq, 512, SMEM>>>(
        (const __half*)pxf, (const __half*)pWkT, bk, pK,
        DM, DM, DM, DM, 1.0f, 0, 0, 0, 0);

    // V^T = WvT * xf^T (+bv per row), batched
    dim3 gvt(SEQ / 256, DM / 128, NB);
    gemm_any<2, true><<<gvt, 512, SMEM>>>(
        (const __half*)pWvT, (const __half*)pxf, bv, pVT,
        DM, DM, DM, SEQ, 1.0f, 0, (long long)SEQ * DM, (long long)DM * SEQ, 0);

    // E = exp(Q * K^T), batched, fp16 out
    dim3 gs(SEQ / 256, SEQ / 128, NB);
    gemm_any<3, true><<<gs, 512, SMEM>>>(
        (const __half*)pQ, (const __half*)pK, nullptr, pE,
        DM, DM, DM, SEQ, 1.0f,
        (long long)SEQ * DM, (long long)SEQ * DM, (long long)SEQ * SEQ, 0);

    // inv[row] = 1 / rowsum(E)
    rowsum_k<<<NB * SEQ, 256>>>((const __half*)pE, (float*)pInv);

    // out = (E * V) * inv[row], batched, fp32 out
    dim3 go(DM / 256, SEQ / 128, NB);
    gemm_any<4, false><<<go, 512, SMEM>>>(
        (const __half*)pE, (const __half*)pVT, (const float*)pInv, out,
        SEQ, SEQ, SEQ, DM, 1.0f,
        (long long)SEQ * SEQ, (long long)DM * SEQ, (long long)SEQ * DM, SEQ);
}